// round 8
// baseline (speedup 1.0000x reference)
#include <cuda_runtime.h>
#include <cuda_bf16.h>
#include <cstdint>

// ---------------------------------------------------------------------------
// GCN 3-layer forward.
// Round 8: GEMM fragment loads via ldmatrix.m8n8.x4 (was scalar LDS.32 —
// LDS-issue-bound). wconv split: W1 on main stream, W2/W3 on side stream.
// Everything else as round 7: CSR build overlapped on side stream, fused
// pairnorm, cp.async double-buffered tensor-core GEMMs, 2-term bf16 split.
// ---------------------------------------------------------------------------

#define NMAX 50000
#define EMAX 800000
#define FMAX 128

__device__ float g_tmp[(size_t)NMAX * FMAX];
__device__ float g_y  [(size_t)NMAX * FMAX];
__device__ float g_colsumA[FMAX];
__device__ float g_colsumB[FMAX];
__device__ int   g_deg [NMAX];
__device__ int   g_off [NMAX + 1];
__device__ int   g_cur [NMAX];
__device__ int   g_csrc[EMAX];
__device__ __nv_bfloat16 g_w1h[128 * 256], g_w1l[128 * 256];
__device__ __nv_bfloat16 g_w2h[128 * 128], g_w2l[128 * 128];
__device__ __nv_bfloat16 g_w3h[ 64 * 128], g_w3l[ 64 * 128];

// ---------------------------------------------------------------------------
// helpers
// ---------------------------------------------------------------------------
__device__ __forceinline__ void cp16(void* s, const void* g) {
    uint32_t sa = (uint32_t)__cvta_generic_to_shared(s);
    asm volatile("cp.async.cg.shared.global [%0], [%1], 16;\n" :: "r"(sa), "l"(g));
}
__device__ __forceinline__ void cp_commit() {
    asm volatile("cp.async.commit_group;\n");
}
__device__ __forceinline__ void mma16816(float* c, const uint32_t* a,
                                         uint32_t b0, uint32_t b1) {
    asm volatile(
        "mma.sync.aligned.m16n8k16.row.col.f32.bf16.bf16.f32 "
        "{%0,%1,%2,%3}, {%4,%5,%6,%7}, {%8,%9}, {%0,%1,%2,%3};\n"
        : "+f"(c[0]), "+f"(c[1]), "+f"(c[2]), "+f"(c[3])
        : "r"(a[0]), "r"(a[1]), "r"(a[2]), "r"(a[3]), "r"(b0), "r"(b1));
}
__device__ __forceinline__ void ldsm4(uint32_t& r0, uint32_t& r1,
                                      uint32_t& r2, uint32_t& r3,
                                      uint32_t addr) {
    asm volatile(
        "ldmatrix.sync.aligned.m8n8.x4.shared.b16 {%0,%1,%2,%3}, [%4];\n"
        : "=r"(r0), "=r"(r1), "=r"(r2), "=r"(r3) : "r"(addr));
}
__device__ __forceinline__ uint32_t pack_bf2(float a, float b) {
    __nv_bfloat162 p = __halves2bfloat162(__float2bfloat16(a), __float2bfloat16(b));
    return *reinterpret_cast<uint32_t*>(&p);
}
__device__ __forceinline__ uint32_t pack_lo2(float a, float b) {
    float ha = __bfloat162float(__float2bfloat16(a));
    float hb = __bfloat162float(__float2bfloat16(b));
    __nv_bfloat162 p = __halves2bfloat162(__float2bfloat16(a - ha),
                                          __float2bfloat16(b - hb));
    return *reinterpret_cast<uint32_t*>(&p);
}

// ---------------------------------------------------------------------------
// W convert: generic (one W -> transposed hi/lo planes)
// ---------------------------------------------------------------------------
__global__ __launch_bounds__(256) void wconv1_kernel(
    const float* __restrict__ W1,
    __nv_bfloat16* __restrict__ wh, __nv_bfloat16* __restrict__ wl)
{
    int idx = blockIdx.x * 256 + threadIdx.x;   // 128 blocks: 128x256
    int n = idx / 256, k = idx % 256;
    float x = W1[(size_t)k * 128 + n];
    __nv_bfloat16 h = __float2bfloat16(x);
    wh[idx] = h;
    wl[idx] = __float2bfloat16(x - __bfloat162float(h));
}

__global__ __launch_bounds__(256) void wconv23_kernel(
    const float* __restrict__ W2, const float* __restrict__ W3,
    __nv_bfloat16* __restrict__ w2h, __nv_bfloat16* __restrict__ w2l,
    __nv_bfloat16* __restrict__ w3h, __nv_bfloat16* __restrict__ w3l)
{
    int b = blockIdx.x;
    const float* W; __nv_bfloat16 *wh, *wl; int K, N, idx;
    if (b < 64) { W = W2; wh = w2h; wl = w2l; K = 128; N = 128; idx = b * 256 + threadIdx.x; }
    else        { W = W3; wh = w3h; wl = w3l; K = 128; N = 64;  idx = (b - 64) * 256 + threadIdx.x; }
    if (idx >= K * N) return;
    int n = idx / K, k = idx % K;
    float x = W[(size_t)k * N + n];
    __nv_bfloat16 h = __float2bfloat16(x);
    wh[idx] = h;
    wl[idx] = __float2bfloat16(x - __bfloat162float(h));
}

// ---------------------------------------------------------------------------
// Tensor-core GEMM, cp.async double-buffered (B), register-prefetch A (fp32),
// ldmatrix fragment loads.
// ---------------------------------------------------------------------------
extern __shared__ uint32_t dynsmem[];

template <int K, int N, bool RELUCM>
__global__ __launch_bounds__(256) void gemm_tc_kernel(
    const float* __restrict__ A, const float* __restrict__ cmean_in,
    float invM, const __nv_bfloat16* __restrict__ wth,
    const __nv_bfloat16* __restrict__ wtl, const float* __restrict__ norm,
    float* __restrict__ C, int M, float* __restrict__ colsum_zero)
{
    constexpr int BM = 128;
    constexpr int BK = 32;
    constexpr int S = 20;
    constexpr int ASZ = BM * S;
    constexpr int BSZ = N * S;
    constexpr int STG = 2 * ASZ + 2 * BSZ;
    constexpr int NS = K / BK;
    constexpr int WARPS_N = (N == 128) ? 2 : 1;
    constexpr int WARPS_M = 8 / WARPS_N;
    constexpr int WM = BM / WARPS_M;
    constexpr int WN = N / WARPS_N;
    constexpr int MT = WM / 16;
    constexpr int NT = WN / 8;

    const int tid = threadIdx.x;
    const int warp = tid >> 5;
    const int lane = tid & 31;
    const int g = lane >> 2;
    const int t = lane & 3;
    const int wm = warp % WARPS_M;
    const int wn = warp / WARPS_M;
    const int row0 = blockIdx.x * BM;

    if (colsum_zero && blockIdx.x == 0 && tid < FMAX) colsum_zero[tid] = 0.0f;

    const uint32_t sb = (uint32_t)__cvta_generic_to_shared(dynsmem);

    // ldmatrix per-lane base addresses (byte, shared space), buf/s added later.
    uint32_t aBase[MT];
#pragma unroll
    for (int mt = 0; mt < MT; mt++) {
        int row = wm * WM + mt * 16 + (lane & 15);
        aBase[mt] = sb + (uint32_t)(row * S + ((lane & 16) ? 4 : 0)) * 4u;
    }
    uint32_t bBase[NT / 2];
#pragma unroll
    for (int jj = 0; jj < NT / 2; jj++) {
        int nrow = wn * WN + (jj * 2 + ((lane >> 4) & 1)) * 8 + (lane & 7);
        bBase[jj] = sb + (uint32_t)(2 * ASZ + nrow * S + ((lane >> 3) & 1) * 4) * 4u;
    }

    float acc[MT][NT][4];
#pragma unroll
    for (int i = 0; i < MT; i++)
#pragma unroll
        for (int j = 0; j < NT; j++)
#pragma unroll
            for (int q = 0; q < 4; q++) acc[i][j][q] = 0.0f;

    auto issueB = [&](int buf, int k0) {
        uint32_t* Bh = dynsmem + buf * STG + 2 * ASZ;
        uint32_t* Bl = Bh + BSZ;
#pragma unroll
        for (int p = 0; p < N * 4 / 256; p++) {
            int idx = tid + p * 256;
            int n = idx >> 2, c = idx & 3;
            cp16(&Bh[n * S + c * 4], wth + (size_t)n * K + k0 + c * 8);
            cp16(&Bl[n * S + c * 4], wtl + (size_t)n * K + k0 + c * 8);
        }
    };
    auto prefA = [&](float4* pv, int k0) {
#pragma unroll
        for (int p = 0; p < 4; p++) {
            int idx = tid + p * 256;
            int m = idx >> 3, c = idx & 7;
            int gr = row0 + m;
            float4 v = make_float4(0.f, 0.f, 0.f, 0.f);
            if (gr < M) {
                v = *(const float4*)(A + (size_t)gr * K + k0 + c * 4);
                if (RELUCM) {
                    const float4 cs = *(const float4*)(cmean_in + k0 + c * 4);
                    v.x = fmaxf(v.x - cs.x * invM, 0.0f);
                    v.y = fmaxf(v.y - cs.y * invM, 0.0f);
                    v.z = fmaxf(v.z - cs.z * invM, 0.0f);
                    v.w = fmaxf(v.w - cs.w * invM, 0.0f);
                }
            }
            pv[p] = v;
        }
    };
    auto stsA = [&](const float4* pv, int buf) {
        uint32_t* Ah = dynsmem + buf * STG;
        uint32_t* Al = Ah + ASZ;
#pragma unroll
        for (int p = 0; p < 4; p++) {
            int idx = tid + p * 256;
            int m = idx >> 3, c = idx & 7;
            int w = m * S + c * 2;
            float4 v = pv[p];
            Ah[w]     = pack_bf2(v.x, v.y);
            Ah[w + 1] = pack_bf2(v.z, v.w);
            Al[w]     = pack_lo2(v.x, v.y);
            Al[w + 1] = pack_lo2(v.z, v.w);
        }
    };
    auto compute = [&](int buf) {
        const uint32_t bufOff = (uint32_t)(buf * STG) * 4u;
#pragma unroll
        for (int s = 0; s < 2; s++) {
            const uint32_t so = bufOff + (uint32_t)(s * 8) * 4u;
            uint32_t ah[MT][4], al[MT][4];
#pragma unroll
            for (int mt = 0; mt < MT; mt++) {
                ldsm4(ah[mt][0], ah[mt][1], ah[mt][2], ah[mt][3],
                      aBase[mt] + so);
                ldsm4(al[mt][0], al[mt][1], al[mt][2], al[mt][3],
                      aBase[mt] + so + (uint32_t)ASZ * 4u);
            }
#pragma unroll
            for (int jj = 0; jj < NT / 2; jj++) {
                int j = jj * 2;
                uint32_t bh[4], bl[4];
                ldsm4(bh[0], bh[1], bh[2], bh[3], bBase[jj] + so);
                ldsm4(bl[0], bl[1], bl[2], bl[3],
                      bBase[jj] + so + (uint32_t)BSZ * 4u);
#pragma unroll
                for (int mt = 0; mt < MT; mt++) {
                    mma16816(acc[mt][j], ah[mt], bh[0], bh[1]);
                    mma16816(acc[mt][j], ah[mt], bl[0], bl[1]);
                    mma16816(acc[mt][j], al[mt], bh[0], bh[1]);
                    mma16816(acc[mt][j + 1], ah[mt], bh[2], bh[3]);
                    mma16816(acc[mt][j + 1], ah[mt], bl[2], bl[3]);
                    mma16816(acc[mt][j + 1], al[mt], bh[2], bh[3]);
                }
            }
        }
    };

    issueB(0, 0);
    cp_commit();
    {
        float4 pv[4];
        prefA(pv, 0);
        stsA(pv, 0);
    }

    for (int s = 0; s < NS; s++) {
        int buf = s & 1;
        float4 pv[4];
        if (s + 1 < NS) {
            prefA(pv, (s + 1) * BK);
            issueB(buf ^ 1, (s + 1) * BK);
            cp_commit();
            asm volatile("cp.async.wait_group 1;\n");
        } else {
            asm volatile("cp.async.wait_group 0;\n");
        }
        __syncthreads();
        compute(buf);
        if (s + 1 < NS) stsA(pv, buf ^ 1);
        __syncthreads();
    }

#pragma unroll
    for (int mt = 0; mt < MT; mt++) {
        int r0 = row0 + wm * WM + mt * 16 + g;
        int r1 = r0 + 8;
        float nm0 = (r0 < M) ? norm[r0] : 0.0f;
        float nm1 = (r1 < M) ? norm[r1] : 0.0f;
#pragma unroll
        for (int nt = 0; nt < NT; nt++) {
            int cc = wn * WN + nt * 8 + 2 * t;
            if (r0 < M) {
                float2 o = make_float2(acc[mt][nt][0] * nm0, acc[mt][nt][1] * nm0);
                *(float2*)(C + (size_t)r0 * N + cc) = o;
            }
            if (r1 < M) {
                float2 o = make_float2(acc[mt][nt][2] * nm1, acc[mt][nt][3] * nm1);
                *(float2*)(C + (size_t)r1 * N + cc) = o;
            }
        }
    }
}

// ---------------------------------------------------------------------------
// CSR build (x8 unrolled)
// ---------------------------------------------------------------------------
__global__ __launch_bounds__(256) void hist_kernel(
    const int* __restrict__ dst, int* __restrict__ deg, int E)
{
    int e = (blockIdx.x * blockDim.x + threadIdx.x) * 8;
    if (e + 7 < E) {
        int4 d0 = *(const int4*)(dst + e);
        int4 d1 = *(const int4*)(dst + e + 4);
        atomicAdd(&deg[d0.x], 1); atomicAdd(&deg[d0.y], 1);
        atomicAdd(&deg[d0.z], 1); atomicAdd(&deg[d0.w], 1);
        atomicAdd(&deg[d1.x], 1); atomicAdd(&deg[d1.y], 1);
        atomicAdd(&deg[d1.z], 1); atomicAdd(&deg[d1.w], 1);
    } else {
        for (int j = e; j < E; j++) atomicAdd(&deg[dst[j]], 1);
    }
}

__global__ __launch_bounds__(1024) void scan_kernel(
    const int* __restrict__ deg, int* __restrict__ off,
    int* __restrict__ cur, int N)
{
    __shared__ int part[1024];
    const int t = threadIdx.x;
    const int chunk = (N + 1023) >> 10;
    const int start = t * chunk;
    const int end = min(start + chunk, N);

    int s = 0;
    for (int i = start; i < end; i++) s += deg[i];
    part[t] = s;
    __syncthreads();
    for (int o = 1; o < 1024; o <<= 1) {
        int v = (t >= o) ? part[t - o] : 0;
        __syncthreads();
        part[t] += v;
        __syncthreads();
    }
    int base = (t == 0) ? 0 : part[t - 1];
    for (int i = start; i < end; i++) {
        off[i] = base;
        cur[i] = base;
        base += deg[i];
    }
    if (t == 1023) off[N] = part[1023];
}

__global__ __launch_bounds__(256) void fill_kernel(
    const int* __restrict__ src, const int* __restrict__ dst,
    int* __restrict__ cur, int* __restrict__ csrc, int E)
{
    int e = (blockIdx.x * blockDim.x + threadIdx.x) * 8;
    if (e + 7 < E) {
        int4 s0 = *(const int4*)(src + e);
        int4 d0 = *(const int4*)(dst + e);
        int4 s1 = *(const int4*)(src + e + 4);
        int4 d1 = *(const int4*)(dst + e + 4);
        csrc[atomicAdd(&cur[d0.x], 1)] = s0.x;
        csrc[atomicAdd(&cur[d0.y], 1)] = s0.y;
        csrc[atomicAdd(&cur[d0.z], 1)] = s0.z;
        csrc[atomicAdd(&cur[d0.w], 1)] = s0.w;
        csrc[atomicAdd(&cur[d1.x], 1)] = s1.x;
        csrc[atomicAdd(&cur[d1.y], 1)] = s1.y;
        csrc[atomicAdd(&cur[d1.z], 1)] = s1.z;
        csrc[atomicAdd(&cur[d1.w], 1)] = s1.w;
    } else {
        for (int j = e; j < E; j++)
            csrc[atomicAdd(&cur[dst[j]], 1)] = src[j];
    }
}

// ---------------------------------------------------------------------------
// Gather-aggregate (pairnorm rownorm fused; colsum for next layer's colmean)
// ---------------------------------------------------------------------------
template <int N4, bool PAIRNORM>
__global__ __launch_bounds__(256) void gather_kernel(
    const float4* __restrict__ tmp, const int* __restrict__ off,
    const int* __restrict__ csrc, const float* __restrict__ norm,
    const float* __restrict__ bias, float4* __restrict__ xout,
    float* __restrict__ colsum, int M)
{
    constexpr int RPB = 256 / N4;
    const int lane = threadIdx.x % N4;
    const int rl = threadIdx.x / N4;

    float4 bb = ((const float4*)bias)[lane];
    float4 lsum = make_float4(0.f, 0.f, 0.f, 0.f);

    for (int r = blockIdx.x * RPB + rl; r < M; r += gridDim.x * RPB) {
        int s0 = __ldg(off + r);
        int s1 = __ldg(off + r + 1);
        float4 acc = make_float4(0.f, 0.f, 0.f, 0.f);
        int i = s0;
        for (; i + 3 < s1; i += 4) {
            int sa = __ldg(csrc + i);
            int sb = __ldg(csrc + i + 1);
            int sc = __ldg(csrc + i + 2);
            int sd = __ldg(csrc + i + 3);
            float4 va = tmp[(size_t)sa * N4 + lane];
            float4 vb = tmp[(size_t)sb * N4 + lane];
            float4 vc = tmp[(size_t)sc * N4 + lane];
            float4 vd = tmp[(size_t)sd * N4 + lane];
            acc.x += (va.x + vb.x) + (vc.x + vd.x);
            acc.y += (va.y + vb.y) + (vc.y + vd.y);
            acc.z += (va.z + vb.z) + (vc.z + vd.z);
            acc.w += (va.w + vb.w) + (vc.w + vd.w);
        }
        for (; i < s1; i++) {
            int sa = __ldg(csrc + i);
            float4 va = tmp[(size_t)sa * N4 + lane];
            acc.x += va.x; acc.y += va.y; acc.z += va.z; acc.w += va.w;
        }
        float nm = norm[r];
        float4 v;
        v.x = acc.x * nm + bb.x;
        v.y = acc.y * nm + bb.y;
        v.z = acc.z * nm + bb.z;
        v.w = acc.w * nm + bb.w;
        if (PAIRNORM) {
            lsum.x += v.x; lsum.y += v.y; lsum.z += v.z; lsum.w += v.w;
            float ss = v.x * v.x + v.y * v.y + v.z * v.z + v.w * v.w;
#pragma unroll
            for (int o = 16; o > 0; o >>= 1)
                ss += __shfl_xor_sync(0xffffffffu, ss, o);
            float rinv = rsqrtf(1e-6f + ss);
            v.x *= rinv; v.y *= rinv; v.z *= rinv; v.w *= rinv;
        }
        xout[(size_t)r * N4 + lane] = v;
    }

    if (PAIRNORM) {
        __shared__ float scol[N4 * 4];
        if (threadIdx.x < N4 * 4) scol[threadIdx.x] = 0.0f;
        __syncthreads();
        atomicAdd(&scol[lane * 4 + 0], lsum.x);
        atomicAdd(&scol[lane * 4 + 1], lsum.y);
        atomicAdd(&scol[lane * 4 + 2], lsum.z);
        atomicAdd(&scol[lane * 4 + 3], lsum.w);
        __syncthreads();
        if (threadIdx.x < N4 * 4)
            atomicAdd(&colsum[threadIdx.x], scol[threadIdx.x]);
    }
}

// ---------------------------------------------------------------------------
// Launch
// ---------------------------------------------------------------------------
extern "C" void kernel_launch(void* const* d_in, const int* in_sizes, int n_in,
                              void* d_out, int out_size)
{
    const float* in_feat = (const float*)d_in[0];
    const int*   src     = (const int*)  d_in[1];
    const int*   dst     = (const int*)  d_in[2];
    const float* norm    = (const float*)d_in[3];
    const float* W1      = (const float*)d_in[4];
    const float* b1      = (const float*)d_in[5];
    const float* W2      = (const float*)d_in[6];
    const float* b2      = (const float*)d_in[7];
    const float* W3      = (const float*)d_in[8];
    const float* b3      = (const float*)d_in[9];
    float* out = (float*)d_out;

    const int M = in_sizes[3];
    const int E = in_sizes[1];
    const float invM = 1.0f / (float)M;

    float *tmp, *y, *colsumA, *colsumB;
    int *deg, *off, *cur, *csrc;
    __nv_bfloat16 *w1h, *w1l, *w2h, *w2l, *w3h, *w3l;
    cudaGetSymbolAddress((void**)&tmp,     g_tmp);
    cudaGetSymbolAddress((void**)&y,       g_y);
    cudaGetSymbolAddress((void**)&colsumA, g_colsumA);
    cudaGetSymbolAddress((void**)&colsumB, g_colsumB);
    cudaGetSymbolAddress((void**)&deg,     g_deg);
    cudaGetSymbolAddress((void**)&off,     g_off);
    cudaGetSymbolAddress((void**)&cur,     g_cur);
    cudaGetSymbolAddress((void**)&csrc,    g_csrc);
    cudaGetSymbolAddress((void**)&w1h,     g_w1h);
    cudaGetSymbolAddress((void**)&w1l,     g_w1l);
    cudaGetSymbolAddress((void**)&w2h,     g_w2h);
    cudaGetSymbolAddress((void**)&w2l,     g_w2l);
    cudaGetSymbolAddress((void**)&w3h,     g_w3h);
    cudaGetSymbolAddress((void**)&w3l,     g_w3l);

    constexpr int SMEM_128 = 2 * (2 * 128 * 20 + 2 * 128 * 20) * 4;  // 81920
    constexpr int SMEM_64  = 2 * (2 * 128 * 20 + 2 * 64  * 20) * 4;  // 61440

    static cudaStream_t side = nullptr;
    static cudaEvent_t evFork = nullptr, evJoin = nullptr;
    if (!side) {
        cudaStreamCreateWithFlags(&side, cudaStreamNonBlocking);
        cudaEventCreateWithFlags(&evFork, cudaEventDisableTiming);
        cudaEventCreateWithFlags(&evJoin, cudaEventDisableTiming);
        cudaFuncSetAttribute(gemm_tc_kernel<256, 128, false>,
                             cudaFuncAttributeMaxDynamicSharedMemorySize, SMEM_128);
        cudaFuncSetAttribute(gemm_tc_kernel<128, 128, true>,
                             cudaFuncAttributeMaxDynamicSharedMemorySize, SMEM_128);
        cudaFuncSetAttribute(gemm_tc_kernel<128, 64, true>,
                             cudaFuncAttributeMaxDynamicSharedMemorySize, SMEM_64);
    }

    const int gemm_blocks = (M + 127) / 128;
    const int GATHER_BLOCKS = (M + 7) / 8;
    const int GATHER_BLOCKS3 = (M + 15) / 16;
    const int E8_BLOCKS = ((E + 7) / 8 + 255) / 256;

    // ---- fork: W2/W3 conversion + CSR build on side stream ----
    cudaEventRecord(evFork, 0);
    cudaStreamWaitEvent(side, evFork, 0);
    wconv23_kernel<<<96, 256, 0, side>>>(W2, W3, w2h, w2l, w3h, w3l);
    cudaMemsetAsync(deg, 0, (size_t)M * sizeof(int), side);
    hist_kernel<<<E8_BLOCKS, 256, 0, side>>>(dst, deg, E);
    scan_kernel<<<1, 1024, 0, side>>>(deg, off, cur, M);
    fill_kernel<<<E8_BLOCKS, 256, 0, side>>>(src, dst, cur, csrc, E);
    cudaEventRecord(evJoin, side);

    // ---- main: W1 conversion + layer-1 GEMM ----
    wconv1_kernel<<<128, 256>>>(W1, w1h, w1l);
    gemm_tc_kernel<256, 128, false><<<gemm_blocks, 256, SMEM_128>>>(
        in_feat, nullptr, 0.0f, w1h, w1l, norm, tmp, M, colsumA);

    // ---- join: gather1 needs CSR + tmp ----
    cudaStreamWaitEvent(0, evJoin, 0);
    gather_kernel<32, true><<<GATHER_BLOCKS, 256>>>(
        (const float4*)tmp, off, csrc, norm, b1, (float4*)y, colsumA, M);

    // ---------------- Layer 2: 128 -> 128 ----------------
    gemm_tc_kernel<128, 128, true><<<gemm_blocks, 256, SMEM_128>>>(
        y, colsumA, invM, w2h, w2l, norm, tmp, M, colsumB);
    gather_kernel<32, true><<<GATHER_BLOCKS, 256>>>(
        (const float4*)tmp, off, csrc, norm, b2, (float4*)y, colsumB, M);

    // ---------------- Layer 3: 128 -> 64 ----------------
    gemm_tc_kernel<128, 64, true><<<gemm_blocks, 256, SMEM_64>>>(
        y, colsumB, invM, w3h, w3l, norm, tmp, M, nullptr);
    gather_kernel<16, false><<<GATHER_BLOCKS3, 256>>>(
        (const float4*)tmp, off, csrc, norm, b3, (float4*)out, nullptr, M);
}